// round 10
// baseline (speedup 1.0000x reference)
#include <cuda_runtime.h>
#include <cuda_bf16.h>
#include <math.h>
#include <stdint.h>

#define SEQ 8
#define FEAT 2048
#define TLEN 28
#define DOUT 1152
#define WAY 5
#define SHOT 5
#define NQ 500
#define NS 25
#define CLIPS (NS + NQ)                /* 525 */
#define NFRAMES (CLIPS * SEQ)          /* 4200 */
#define NROWS (CLIPS * TLEN)           /* 14700 */
#define SROWS (NS * TLEN)              /* 700 */
#define QROWS (NQ * TLEN)              /* 14000 */
#define CLS 140                        /* SHOT*TLEN */
#define LN_EPS 1e-5f
#define WSTK (4 * DOUT)                /* 4608 */
#define ABLD 720                       /* bf16 attn row stride (5*144) */
#define CPAD 144                       /* padded class block stride */
#define QYT 110                        /* QROWS m-tiles */

// ------------------------- scratch (device globals) -----------------------
__device__ __nv_bfloat16  d_Xh [NFRAMES * FEAT];
__device__ __nv_bfloat16  d_WT [WSTK * FEAT];
__device__ __nv_bfloat16  d_Ph [NFRAMES * WSTK];
__device__ __nv_bfloat16  d_KSh[NROWS * DOUT];
__device__ __nv_bfloat16  d_VSh[NROWS * DOUT];
__device__ float          d_VN [NROWS];
__device__ float          d_QK [QROWS * SROWS];           // raw scores (fp32)
__device__ __nv_bfloat16  d_Ab [QROWS * ABLD];            // attn bf16, padded blocks
__device__ float          d_QV [QROWS * SROWS];
__device__ float          d_D2 [WAY * QROWS * 8];         // fused distance partials
__device__ __nv_bfloat16  d_SSh[WAY * CLS * CPAD];

__constant__ int c_TA[TLEN] = {0,0,0,0,0,0,0,1,1,1,1,1,1,2,2,2,2,2,3,3,3,3,4,4,4,5,5,6};
__constant__ int c_TB[TLEN] = {1,2,3,4,5,6,7,2,3,4,5,6,7,3,4,5,6,7,4,5,6,7,5,6,7,6,7,7};

__device__ __forceinline__ uint32_t smem_u32(const void* p) {
    uint32_t a;
    asm("{ .reg .u64 t; cvta.to.shared.u64 t, %1; cvt.u32.u64 %0, t; }" : "=r"(a) : "l"(p));
    return a;
}
__device__ __forceinline__ void cp16(uint32_t dst, const void* src, int sz) {
    asm volatile("cp.async.cg.shared.global [%0], [%1], 16, %2;"
                 :: "r"(dst), "l"(src), "r"(sz) : "memory");
}

// ------------------------- kernel 1: gather frames + inline PE -> bf16 ----
__global__ void build_x(const float* __restrict__ sup, const float* __restrict__ qry) {
    long e = ((long)blockIdx.x * blockDim.x + threadIdx.x) * 8;
    if (e >= (long)NFRAMES * FEAT) return;
    int f = (int)(e / FEAT);
    int d = (int)(e % FEAT);
    int frame = f % SEQ;
    const float* src = (f < NS * SEQ) ? (sup + (long)f * FEAT + d)
                                      : (qry + (long)(f - NS * SEQ) * FEAT + d);
    float4 a = *(const float4*)src;
    float4 b = *(const float4*)(src + 4);
    float x[8] = {a.x, a.y, a.z, a.w, b.x, b.y, b.z, b.w};
    const float coef = -logf(10000.0f) / (float)FEAT;
    #pragma unroll
    for (int p = 0; p < 4; p++) {
        float div = __expf((float)(d + 2 * p) * coef);
        float s, c;
        __sincosf((float)frame * div, &s, &c);
        x[2 * p]     += s;
        x[2 * p + 1] += c;
    }
    __nv_bfloat162 h[4];
    #pragma unroll
    for (int p = 0; p < 4; p++) h[p] = __floats2bfloat162_rn(x[2 * p], x[2 * p + 1]);
    *(uint4*)(d_Xh + e) = *(uint4*)h;
}

// ------------------------- kernel 2: weight transpose -> bf16 -------------
__global__ void wtrans(const float* __restrict__ kw, const float* __restrict__ vw) {
    __shared__ float t[32][33];
    int p  = blockIdx.z;
    int n0 = blockIdx.x * 32, k0 = blockIdx.y * 32;
    const float* W = ((p < 2) ? kw : vw) + (size_t)((p & 1) * FEAT) * DOUT;
    #pragma unroll
    for (int i = 0; i < 4; i++) {
        int k = k0 + threadIdx.y + i * 8;
        t[threadIdx.y + i * 8][threadIdx.x] = W[(size_t)k * DOUT + n0 + threadIdx.x];
    }
    __syncthreads();
    #pragma unroll
    for (int i = 0; i < 4; i++) {
        int n = n0 + threadIdx.y + i * 8;
        d_WT[(size_t)(p * DOUT + n) * FEAT + k0 + threadIdx.x] =
            __float2bfloat16(t[threadIdx.x][threadIdx.y + i * 8]);
    }
}

// ------------------------- 128x288 projection GEMM (32x144 warp tiles) ----
// C[M,N] = A[M,K] @ B[N,K]^T, bf16 out. BK=64, 3 stages, 1 CTA/SM.
// Requires: N = 16*288 exactly (always in-bounds), K multiple of 64.
#define PG_STRIDE 72
#define PG_ABYTES (128 * PG_STRIDE * 2)          /* 18432 */
#define PG_BBYTES (288 * PG_STRIDE * 2)          /* 41472 */
#define PG_STAGE  (PG_ABYTES + PG_BBYTES)        /* 59904 */
#define PG_SMEM   (3 * PG_STAGE)                 /* 179712 */

__global__ void __launch_bounds__(256, 1) pgemm(const __nv_bfloat16* __restrict__ A,
                                                const __nv_bfloat16* __restrict__ B,
                                                __nv_bfloat16* __restrict__ C,
                                                int M, int N, int K,
                                                int lda, int ldb, int ldc)
{
    extern __shared__ __align__(16) char smem[];
    const uint32_t sbase = smem_u32(smem);
    const int tid  = threadIdx.x;
    const int wid  = tid >> 5, lane = tid & 31;
    const int wm   = wid >> 1, wn = wid & 1;          // 4x2 warps, warp tile 32x144
    const int m0   = blockIdx.y * 128, n0 = blockIdx.x * 288;
    const int nk   = K >> 6;

    float acc[2][18][4];
    #pragma unroll
    for (int i = 0; i < 2; i++)
        #pragma unroll
        for (int j = 0; j < 18; j++)
            #pragma unroll
            for (int r = 0; r < 4; r++) acc[i][j][r] = 0.f;

    // ---- load setup: ch = 16B chunk (0..7), r0 = row (0..31) ----
    const int ch = tid & 7;
    const int r0 = tid >> 3;
    const __nv_bfloat16* Abase = A + (size_t)m0 * lda + ch * 8;
    const __nv_bfloat16* Bbase = B + (size_t)n0 * ldb + ch * 8;
    const uint32_t dbase = (uint32_t)(r0 * (PG_STRIDE * 2) + ch * 16);

    auto load_stage = [&](int sidx, int kc) {
        const int k0 = kc * 64;
        const uint32_t st = sbase + sidx * PG_STAGE;
        #pragma unroll
        for (int g = 0; g < 4; g++) {
            int row = r0 + 32 * g;
            int sz = (m0 + row < M) ? 16 : 0;
            cp16(st + dbase + g * (32 * PG_STRIDE * 2),
                 Abase + (size_t)row * lda + k0, sz);
        }
        #pragma unroll
        for (int g = 0; g < 9; g++) {
            int row = r0 + 32 * g;
            cp16(st + PG_ABYTES + dbase + g * (32 * PG_STRIDE * 2),
                 Bbase + (size_t)row * ldb + k0, 16);
        }
        asm volatile("cp.async.commit_group;" ::: "memory");
    };

    // ---- hoisted fragment smem offsets ----
    uint32_t offA[2], offB[9];
    #pragma unroll
    for (int mt = 0; mt < 2; mt++)
        offA[mt] = (uint32_t)(((wm * 32 + mt * 16 + (lane & 15)) * PG_STRIDE
                               + (lane >> 4) * 8) * 2);
    #pragma unroll
    for (int nh = 0; nh < 9; nh++) {
        int nrow = wn * 144 + nh * 16 + ((lane >> 4) * 8) + (lane & 7);
        int kof  = ((lane >> 3) & 1) * 8;
        offB[nh] = (uint32_t)((nrow * PG_STRIDE + kof) * 2) + PG_ABYTES;
    }

    const int pst = nk < 2 ? nk : 2;
    for (int s = 0; s < pst; s++) load_stage(s, s);

    for (int i = 0; i < nk; i++) {
        if (i + 1 < nk) asm volatile("cp.async.wait_group 1;" ::: "memory");
        else            asm volatile("cp.async.wait_group 0;" ::: "memory");
        __syncthreads();

        if (i + 2 < nk) load_stage((i + 2) % 3, i + 2);

        const uint32_t stg = sbase + (i % 3) * PG_STAGE;

        #pragma unroll
        for (int ks = 0; ks < 4; ks++) {
            uint32_t a[2][4], b[18][2];
            #pragma unroll
            for (int nh = 0; nh < 9; nh++) {
                uint32_t addr = stg + offB[nh] + ks * 32;
                uint32_t q0, q1, q2, q3;
                asm volatile("ldmatrix.sync.aligned.m8n8.x4.shared.b16 {%0,%1,%2,%3}, [%4];"
                             : "=r"(q0), "=r"(q1), "=r"(q2), "=r"(q3) : "r"(addr));
                b[nh * 2][0] = q0;     b[nh * 2][1] = q1;
                b[nh * 2 + 1][0] = q2; b[nh * 2 + 1][1] = q3;
            }
            {
                uint32_t addr = stg + offA[0] + ks * 32;
                asm volatile("ldmatrix.sync.aligned.m8n8.x4.shared.b16 {%0,%1,%2,%3}, [%4];"
                             : "=r"(a[0][0]), "=r"(a[0][1]), "=r"(a[0][2]), "=r"(a[0][3])
                             : "r"(addr));
            }
            #pragma unroll
            for (int mt = 0; mt < 2; mt++) {
                if (mt < 1) {
                    uint32_t addr = stg + offA[1] + ks * 32;
                    asm volatile("ldmatrix.sync.aligned.m8n8.x4.shared.b16 {%0,%1,%2,%3}, [%4];"
                                 : "=r"(a[1][0]), "=r"(a[1][1]),
                                   "=r"(a[1][2]), "=r"(a[1][3])
                                 : "r"(addr));
                }
                #pragma unroll
                for (int nt = 0; nt < 18; nt++) {
                    asm volatile(
                        "mma.sync.aligned.m16n8k16.row.col.f32.bf16.bf16.f32 "
                        "{%0,%1,%2,%3}, {%4,%5,%6,%7}, {%8,%9}, {%0,%1,%2,%3};"
                        : "+f"(acc[mt][nt][0]), "+f"(acc[mt][nt][1]),
                          "+f"(acc[mt][nt][2]), "+f"(acc[mt][nt][3])
                        : "r"(a[mt][0]), "r"(a[mt][1]), "r"(a[mt][2]), "r"(a[mt][3]),
                          "r"(b[nt][0]), "r"(b[nt][1]));
                }
            }
        }
    }

    #pragma unroll
    for (int mt = 0; mt < 2; mt++) {
        #pragma unroll
        for (int nt = 0; nt < 18; nt++) {
            int mb = m0 + wm * 32 + mt * 16 + (lane >> 2);
            int nb = n0 + wn * 144 + nt * 8 + (lane & 3) * 2;
            if (mb < M)
                *(__nv_bfloat162*)(C + (size_t)mb * ldc + nb) =
                    __floats2bfloat162_rn(acc[mt][nt][0], acc[mt][nt][1]);
            if (mb + 8 < M)
                *(__nv_bfloat162*)(C + (size_t)(mb + 8) * ldc + nb) =
                    __floats2bfloat162_rn(acc[mt][nt][2], acc[mt][nt][3]);
        }
    }
}

// ------------------------- bf16 mma.sync NT GEMM (batched, BK=64) ---------
// MODE 2: fused distance epilogue.  MODE 3: merged QK/QV/SS launch.
#define MG_STRIDE 72
#define MG_STAGE_B (128 * MG_STRIDE * 2)
#define MG_SMEM (3 * 2 * MG_STAGE_B)

struct BPtr { const __nv_bfloat16* A; const __nv_bfloat16* B; void* C; const float* Q; };
struct BatchArg { BPtr p[5]; };

template<int MODE>
__global__ void __launch_bounds__(256, 2) mgemm(BatchArg ba,
                                                int Ma, int Na, int Ka,
                                                int lda_a, int ldb_a, int ldc_a,
                                                float* __restrict__ Df)
{
    extern __shared__ __align__(16) char smem[];
    int m0, n0, M, N, K, lda, ldb, ldc;
    const __nv_bfloat16 *A, *B;
    void* Cv = nullptr;
    bool outbf;
    if (MODE == 3) {
        K = DOUT; lda = DOUT; ldb = DOUT;
        if (blockIdx.y < QYT) {
            const BPtr& bp = ba.p[blockIdx.z];
            A = bp.A; B = bp.B; Cv = bp.C;
            M = QROWS; N = SROWS; ldc = SROWS; outbf = false;
            m0 = blockIdx.y * 128; n0 = blockIdx.x * 128;
        } else {
            int idx = ((blockIdx.y - QYT) * 2 + blockIdx.z) * 6 + blockIdx.x;
            if (idx >= 20) return;
            int c = idx >> 2, sub = idx & 3;
            m0 = (sub >> 1) * 128; n0 = (sub & 1) * 128;
            A = ba.p[2].A + (size_t)c * CLS * DOUT;
            B = A;
            Cv = (void*)((__nv_bfloat16*)ba.p[2].C + (size_t)c * CLS * CPAD);
            M = CLS; N = CLS; ldc = CPAD; outbf = true;
        }
    } else {
        const BPtr& bp = ba.p[blockIdx.z];
        A = bp.A; B = bp.B; Cv = bp.C;
        M = Ma; N = Na; K = Ka; lda = lda_a; ldb = ldb_a; ldc = ldc_a;
        outbf = false;
        m0 = blockIdx.y * 128; n0 = blockIdx.x * 128;
    }

    const uint32_t sbase = smem_u32(smem);
    const int tid  = threadIdx.x;
    const int wid  = tid >> 5, lane = tid & 31;
    const int wm   = wid >> 2, wn = wid & 3;
    const int nk   = (K + 63) >> 6;

    float acc[4][4][4];
    #pragma unroll
    for (int i = 0; i < 4; i++)
        #pragma unroll
        for (int j = 0; j < 4; j++)
            #pragma unroll
            for (int r = 0; r < 4; r++) acc[i][j][r] = 0.f;

    const int ch = tid & 7;
    const int r0 = tid >> 3;
    bool vA[4], vB[4];
    const __nv_bfloat16 *pA[4], *pB[4];
    uint32_t dA[4], dB[4];
    #pragma unroll
    for (int g = 0; g < 4; g++) {
        int row = r0 + 32 * g;
        vA[g] = (m0 + row) < M;
        vB[g] = (n0 + row) < N;
        pA[g] = A + (size_t)(vA[g] ? m0 + row : 0) * lda + ch * 8;
        pB[g] = B + (size_t)(vB[g] ? n0 + row : 0) * ldb + ch * 8;
        dA[g] = (uint32_t)(row * (MG_STRIDE * 2) + ch * 16);
        dB[g] = dA[g] + MG_STAGE_B;
    }

    auto load_stage = [&](int sidx, int kc) {
        const int k0 = kc * 64;
        const uint32_t st = sbase + sidx * (2 * MG_STAGE_B);
        int szk;
        if (k0 + 64 <= K) szk = 16;
        else {
            int ke  = k0 + ch * 8;
            int rem = (K - ke) * 2;
            szk = rem >= 16 ? 16 : (rem > 0 ? rem : 0);
        }
        #pragma unroll
        for (int g = 0; g < 4; g++) {
            cp16(st + dA[g], pA[g] + k0, vA[g] ? szk : 0);
            cp16(st + dB[g], pB[g] + k0, vB[g] ? szk : 0);
        }
        asm volatile("cp.async.commit_group;" ::: "memory");
    };

    uint32_t offA[4], offB[2];
    #pragma unroll
    for (int mt = 0; mt < 4; mt++)
        offA[mt] = (uint32_t)(((wm * 64 + mt * 16 + (lane & 15)) * MG_STRIDE
                               + (lane >> 4) * 8) * 2);
    #pragma unroll
    for (int nh = 0; nh < 2; nh++) {
        int nrow = nh * 16 + ((lane >> 4) * 8) + (lane & 7);
        int kof  = ((lane >> 3) & 1) * 8;
        offB[nh] = (uint32_t)(((wn * 32 + nrow) * MG_STRIDE + kof) * 2) + MG_STAGE_B;
    }

    const int pst = nk < 2 ? nk : 2;
    for (int s = 0; s < pst; s++) load_stage(s, s);

    for (int i = 0; i < nk; i++) {
        if (i + 1 < nk) asm volatile("cp.async.wait_group 1;" ::: "memory");
        else            asm volatile("cp.async.wait_group 0;" ::: "memory");
        __syncthreads();

        if (i + 2 < nk) load_stage((i + 2) % 3, i + 2);

        const uint32_t stg = sbase + (i % 3) * (2 * MG_STAGE_B);

        #pragma unroll
        for (int ks = 0; ks < 4; ks++) {
            uint32_t a[4][4], b[4][2];
            #pragma unroll
            for (int nh = 0; nh < 2; nh++) {
                uint32_t addr = stg + offB[nh] + ks * 32;
                uint32_t q0, q1, q2, q3;
                asm volatile("ldmatrix.sync.aligned.m8n8.x4.shared.b16 {%0,%1,%2,%3}, [%4];"
                             : "=r"(q0), "=r"(q1), "=r"(q2), "=r"(q3) : "r"(addr));
                b[nh * 2][0] = q0;     b[nh * 2][1] = q1;
                b[nh * 2 + 1][0] = q2; b[nh * 2 + 1][1] = q3;
            }
            {
                uint32_t addr = stg + offA[0] + ks * 32;
                asm volatile("ldmatrix.sync.aligned.m8n8.x4.shared.b16 {%0,%1,%2,%3}, [%4];"
                             : "=r"(a[0][0]), "=r"(a[0][1]), "=r"(a[0][2]), "=r"(a[0][3])
                             : "r"(addr));
            }
            #pragma unroll
            for (int mt = 0; mt < 4; mt++) {
                if (mt < 3) {
                    uint32_t addr = stg + offA[mt + 1] + ks * 32;
                    asm volatile("ldmatrix.sync.aligned.m8n8.x4.shared.b16 {%0,%1,%2,%3}, [%4];"
                                 : "=r"(a[mt+1][0]), "=r"(a[mt+1][1]),
                                   "=r"(a[mt+1][2]), "=r"(a[mt+1][3])
                                 : "r"(addr));
                }
                #pragma unroll
                for (int nt = 0; nt < 4; nt++) {
                    asm volatile(
                        "mma.sync.aligned.m16n8k16.row.col.f32.bf16.bf16.f32 "
                        "{%0,%1,%2,%3}, {%4,%5,%6,%7}, {%8,%9}, {%0,%1,%2,%3};"
                        : "+f"(acc[mt][nt][0]), "+f"(acc[mt][nt][1]),
                          "+f"(acc[mt][nt][2]), "+f"(acc[mt][nt][3])
                        : "r"(a[mt][0]), "r"(a[mt][1]), "r"(a[mt][2]), "r"(a[mt][3]),
                          "r"(b[nt][0]), "r"(b[nt][1]));
                }
            }
        }
    }

    if (MODE == 2) {
        const float* __restrict__ Q = ba.p[blockIdx.z].Q;
        float* Dz = Df + (size_t)blockIdx.z * (size_t)M * 8;
        #pragma unroll
        for (int mt = 0; mt < 4; mt++) {
            #pragma unroll
            for (int r = 0; r < 2; r++) {
                int m = m0 + wm * 64 + mt * 16 + (lane >> 2) + r * 8;
                float p = 0.f;
                if (m < M) {
                    #pragma unroll
                    for (int nt = 0; nt < 4; nt++) {
                        int nb = n0 + wn * 32 + nt * 8 + (lane & 3) * 2;
                        if (nb < N) {
                            float at0 = __bfloat162float(A[(size_t)m * lda + nb]);
                            p += at0 * (acc[mt][nt][r * 2] - 2.f * Q[(size_t)m * ldc + nb]);
                            if (nb + 1 < N) {
                                float at1 = __bfloat162float(A[(size_t)m * lda + nb + 1]);
                                p += at1 * (acc[mt][nt][r * 2 + 1] - 2.f * Q[(size_t)m * ldc + nb + 1]);
                            }
                        }
                    }
                }
                p += __shfl_xor_sync(0xffffffffu, p, 1);
                p += __shfl_xor_sync(0xffffffffu, p, 2);
                if (m < M && (lane & 3) == 0)
                    Dz[(size_t)m * 8 + blockIdx.x * 4 + wn] = p;
            }
        }
        return;
    }

    #pragma unroll
    for (int mt = 0; mt < 4; mt++) {
        #pragma unroll
        for (int nt = 0; nt < 4; nt++) {
            int mb = m0 + wm * 64 + mt * 16 + (lane >> 2);
            int nb = n0 + wn * 32 + nt * 8 + (lane & 3) * 2;
            if (nb >= N) continue;
            if (outbf) {
                __nv_bfloat16* C = (__nv_bfloat16*)Cv;
                if (mb < M)
                    *(__nv_bfloat162*)(C + (size_t)mb * ldc + nb) =
                        __floats2bfloat162_rn(acc[mt][nt][0], acc[mt][nt][1]);
                if (mb + 8 < M)
                    *(__nv_bfloat162*)(C + (size_t)(mb + 8) * ldc + nb) =
                        __floats2bfloat162_rn(acc[mt][nt][2], acc[mt][nt][3]);
            } else {
                float* C = (float*)Cv;
                if (mb < M)
                    *(float2*)(C + (size_t)mb * ldc + nb) =
                        make_float2(acc[mt][nt][0], acc[mt][nt][1]);
                if (mb + 8 < M)
                    *(float2*)(C + (size_t)(mb + 8) * ldc + nb) =
                        make_float2(acc[mt][nt][2], acc[mt][nt][3]);
            }
        }
    }
}

// ------------------------- kernel 3: clip-level assemble ------------------
#define ASM_SMEM (8 * WSTK * 2)        /* 73728 bytes */

__global__ void __launch_bounds__(1024) assemble(const float* __restrict__ k_b,
                                                 const float* __restrict__ v_b,
                                                 const float* __restrict__ gamma,
                                                 const float* __restrict__ beta)
{
    extern __shared__ __align__(16) __nv_bfloat16 sf[];
    int clip = blockIdx.x;
    int tid = threadIdx.x;

    const uint4* src = (const uint4*)(d_Ph + (size_t)clip * 8 * WSTK);
    uint4* dst = (uint4*)sf;
    #pragma unroll
    for (int i = 0; i < 5; i++) {
        int idx = tid + 1024 * i;
        if (idx < (8 * WSTK) / 8) dst[idx] = src[idx];
    }
    __syncthreads();

    int w = tid >> 5, lane = tid & 31;
    if (w >= TLEN) return;
    int fa = c_TA[w], fb = c_TB[w];
    int r = (clip < NS) ? clip * TLEN + w : SROWS + (clip - NS) * TLEN + w;

    const __nv_bfloat162* A2 = (const __nv_bfloat162*)(sf + fa * WSTK);
    const __nv_bfloat162* B2 = (const __nv_bfloat162*)(sf + fb * WSTK);
    const float2* kb2 = (const float2*)k_b;
    const float2* vb2 = (const float2*)v_b;
    __nv_bfloat162* vout = (__nv_bfloat162*)(d_VSh + (size_t)r * DOUT);

    float s1 = 0.f, s2 = 0.f, vn = 0.f;
    #pragma unroll 6
    for (int i = 0; i < 18; i++) {
        int j2 = lane + 32 * i;
        __nv_bfloat162 ka = A2[j2];
        __nv_bfloat162 kb = B2[DOUT / 2 + j2];
        float2 kbias = kb2[j2];
        float k0 = __low2float(ka)  + __low2float(kb)  + kbias.x;
        float k1 = __high2float(ka) + __high2float(kb) + kbias.y;
        s1 += k0 + k1; s2 += k0 * k0 + k1 * k1;
        __nv_bfloat162 va = A2[DOUT + j2];
        __nv_bfloat162 vb = B2[3 * DOUT / 2 + j2];
        float2 vbias = vb2[j2];
        float v0 = __low2float(va)  + __low2float(vb)  + vbias.x;
        float v1 = __high2float(va) + __high2float(vb) + vbias.y;
        vn += v0 * v0 + v1 * v1;
        vout[j2] = __floats2bfloat162_rn(v0, v1);
    }
    #pragma unroll
    for (int s = 16; s > 0; s >>= 1) {
        s1 += __shfl_xor_sync(0xffffffffu, s1, s);
        s2 += __shfl_xor_sync(0xffffffffu, s2, s);
        vn += __shfl_xor_sync(0xffffffffu, vn, s);
    }
    float mu  = s1 / (float)DOUT;
    float var = s2 / (float)DOUT - mu * mu;
    float inv = rsqrtf(var + LN_EPS);

    const float2* g2 = (const float2*)gamma;
    const float2* b2 = (const float2*)beta;
    __nv_bfloat162* kout = (__nv_bfloat162*)(d_KSh + (size_t)r * DOUT);
    #pragma unroll 6
    for (int i = 0; i < 18; i++) {
        int j2 = lane + 32 * i;
        __nv_bfloat162 ka = A2[j2];
        __nv_bfloat162 kb = B2[DOUT / 2 + j2];
        float2 kbias = kb2[j2];
        float k0 = __low2float(ka)  + __low2float(kb)  + kbias.x;
        float k1 = __high2float(ka) + __high2float(kb) + kbias.y;
        float2 g = g2[j2], bt = b2[j2];
        kout[j2] = __floats2bfloat162_rn((k0 - mu) * inv * g.x + bt.x,
                                         (k1 - mu) * inv * g.y + bt.y);
    }
    if (lane == 0) d_VN[r] = vn;
}

// ------------------------- kernel 4: softmax (bf16 out only) --------------
__global__ void softmax_k(float scale) {
    int row  = blockIdx.x;
    int c    = threadIdx.x >> 5;
    int lane = threadIdx.x & 31;
    const float* p = d_QK + (size_t)row * SROWS + c * CLS;
    __nv_bfloat16* pb = d_Ab + (size_t)row * ABLD + c * CPAD;

    float v[5];
    float mx = -1e30f;
    #pragma unroll
    for (int i = 0; i < 5; i++) {
        int j = lane + 32 * i;
        v[i] = (j < CLS) ? p[j] * scale : -1e30f;
        mx = fmaxf(mx, v[i]);
    }
    #pragma unroll
    for (int s = 16; s > 0; s >>= 1) mx = fmaxf(mx, __shfl_xor_sync(0xffffffffu, mx, s));
    float sum = 0.f;
    #pragma unroll
    for (int i = 0; i < 5; i++) {
        int j = lane + 32 * i;
        if (j < CLS) { v[i] = expf(v[i] - mx); sum += v[i]; }
    }
    #pragma unroll
    for (int s = 16; s > 0; s >>= 1) sum += __shfl_xor_sync(0xffffffffu, sum, s);
    float invs = 1.0f / sum;
    #pragma unroll
    for (int i = 0; i < 5; i++) {
        int j = lane + 32 * i;
        if (j < CLS) pb[j] = __float2bfloat16(v[i] * invs);
    }
}

// ------------------------- kernel 5: tiny final reduction -----------------
__global__ void final_k(const float* __restrict__ gt, const float* __restrict__ tw,
                        float* __restrict__ out)
{
    int q = blockIdx.x;
    int c = threadIdx.x >> 5;
    int lane = threadIdx.x & 31;
    float temp = gt[0] * tw[0];

    float tot = 0.f;
    if (lane < TLEN) {
        tot = d_VN[SROWS + q * TLEN + lane];
        const float* dd = d_D2 + ((size_t)c * QROWS + q * TLEN + lane) * 8;
        float4 x = *(const float4*)dd;
        float4 y = *(const float4*)(dd + 4);
        tot += x.x + x.y + x.z + x.w + y.x + y.y + y.z + y.w;
    }
    #pragma unroll
    for (int s = 16; s > 0; s >>= 1) tot += __shfl_xor_sync(0xffffffffu, tot, s);
    if (lane == 0) out[q * WAY + c] = -(tot / (float)TLEN) * temp;
}

// ------------------------- launch -----------------------------------------
extern "C" void kernel_launch(void* const* d_in, const int* in_sizes, int n_in,
                              void* d_out, int out_size) {
    const float* sup   = (const float*)d_in[0];
    const float* qry   = (const float*)d_in[2];
    const float* k_w   = (const float*)d_in[3];
    const float* k_b   = (const float*)d_in[4];
    const float* v_w   = (const float*)d_in[5];
    const float* v_b   = (const float*)d_in[6];
    const float* gamma = (const float*)d_in[7];
    const float* beta  = (const float*)d_in[8];
    const float* gt    = (const float*)d_in[9];
    const float* tw    = (const float*)d_in[10];
    float* out = (float*)d_out;

    __nv_bfloat16 *pXh, *pWT, *pPh, *pKSh, *pVSh, *pAb, *pSSh;
    float *pQK, *pQV, *pD2;
    cudaGetSymbolAddress((void**)&pXh,  d_Xh);
    cudaGetSymbolAddress((void**)&pWT,  d_WT);
    cudaGetSymbolAddress((void**)&pPh,  d_Ph);
    cudaGetSymbolAddress((void**)&pKSh, d_KSh);
    cudaGetSymbolAddress((void**)&pVSh, d_VSh);
    cudaGetSymbolAddress((void**)&pQK,  d_QK);
    cudaGetSymbolAddress((void**)&pQV,  d_QV);
    cudaGetSymbolAddress((void**)&pD2,  d_D2);
    cudaGetSymbolAddress((void**)&pAb,  d_Ab);
    cudaGetSymbolAddress((void**)&pSSh, d_SSh);

    cudaFuncSetAttribute(pgemm,    cudaFuncAttributeMaxDynamicSharedMemorySize, PG_SMEM);
    cudaFuncSetAttribute(mgemm<2>, cudaFuncAttributeMaxDynamicSharedMemorySize, MG_SMEM);
    cudaFuncSetAttribute(mgemm<3>, cudaFuncAttributeMaxDynamicSharedMemorySize, MG_SMEM);
    cudaFuncSetAttribute(assemble, cudaFuncAttributeMaxDynamicSharedMemorySize, ASM_SMEM);

    build_x<<<(NFRAMES * FEAT / 8 + 255) / 256, 256>>>(sup, qry);
    wtrans<<<dim3(DOUT / 32, FEAT / 32, 4), dim3(32, 8)>>>(k_w, v_w);

    // Projections (bf16 out): Ph[4200, 4608] = Xh @ WT^T  (128x288 tiles)
    {
        dim3 g(WSTK / 288, (NFRAMES + 127) / 128);     // 16 x 33 = 528 tiles
        pgemm<<<g, 256, PG_SMEM>>>(pXh, pWT, pPh, NFRAMES, WSTK, FEAT, FEAT, FEAT, WSTK);
    }

    assemble<<<CLIPS, 1024, ASM_SMEM>>>(k_b, v_b, gamma, beta);

    // Merged QK + QV + per-class SS Gram (grid (6, 112, 2))
    {
        BatchArg ba = {};
        ba.p[0] = { pKSh + (size_t)SROWS * DOUT, pKSh, (void*)pQK, nullptr };
        ba.p[1] = { pVSh + (size_t)SROWS * DOUT, pVSh, (void*)pQV, nullptr };
        ba.p[2] = { pVSh, nullptr, (void*)pSSh, nullptr };
        dim3 g(6, QYT + 2, 2);
        mgemm<3><<<g, 256, MG_SMEM>>>(ba, 0, 0, 0, 0, 0, 0, nullptr);
    }

    softmax_k<<<QROWS, 160>>>(1.0f / sqrtf((float)DOUT));

    // Fused H + distance partials (z=5)
    {
        BatchArg ba = {};
        for (int c = 0; c < WAY; c++)
            ba.p[c] = { pAb + (size_t)c * CPAD,
                        pSSh + (size_t)c * CLS * CPAD,
                        nullptr,
                        pQV + (size_t)c * CLS };
        dim3 g((CLS + 127) / 128, (QROWS + 127) / 128, WAY);
        mgemm<2><<<g, 256, MG_SMEM>>>(ba, QROWS, CLS, CLS, ABLD, CPAD, SROWS, pD2);
    }

    final_k<<<NQ, 160>>>(gt, tw, out);
}

// round 11
// speedup vs baseline: 1.0280x; 1.0280x over previous
#include <cuda_runtime.h>
#include <cuda_bf16.h>
#include <math.h>
#include <stdint.h>

#define SEQ 8
#define FEAT 2048
#define TLEN 28
#define DOUT 1152
#define WAY 5
#define SHOT 5
#define NQ 500
#define NS 25
#define CLIPS (NS + NQ)                /* 525 */
#define NFRAMES (CLIPS * SEQ)          /* 4200 */
#define NROWS (CLIPS * TLEN)           /* 14700 */
#define SROWS (NS * TLEN)              /* 700 */
#define QROWS (NQ * TLEN)              /* 14000 */
#define CLS 140                        /* SHOT*TLEN */
#define LN_EPS 1e-5f
#define WSTK (4 * DOUT)                /* 4608 */
#define ABLD 720                       /* bf16 attn row stride (5*144) */
#define CPAD 144                       /* padded class block stride */
#define QYT 110                        /* QROWS m-tiles */

// ------------------------- scratch (device globals) -----------------------
__device__ __nv_bfloat16  d_Xh [NFRAMES * FEAT];
__device__ __nv_bfloat16  d_WT [WSTK * FEAT];
__device__ __nv_bfloat16  d_Ph [NFRAMES * WSTK];
__device__ __nv_bfloat16  d_KSh[NROWS * DOUT];
__device__ __nv_bfloat16  d_VSh[NROWS * DOUT];
__device__ float          d_VN [NROWS];
__device__ float          d_QK [QROWS * SROWS];           // raw scores (fp32)
__device__ __nv_bfloat16  d_Ab [QROWS * ABLD];            // attn bf16, padded blocks
__device__ float          d_QV [QROWS * SROWS];
__device__ float          d_D2 [WAY * QROWS * 8];         // fused distance partials
__device__ __nv_bfloat16  d_SSh[WAY * CLS * CPAD];

__constant__ int c_TA[TLEN] = {0,0,0,0,0,0,0,1,1,1,1,1,1,2,2,2,2,2,3,3,3,3,4,4,4,5,5,6};
__constant__ int c_TB[TLEN] = {1,2,3,4,5,6,7,2,3,4,5,6,7,3,4,5,6,7,4,5,6,7,5,6,7,6,7,7};

__device__ __forceinline__ uint32_t smem_u32(const void* p) {
    uint32_t a;
    asm("{ .reg .u64 t; cvta.to.shared.u64 t, %1; cvt.u32.u64 %0, t; }" : "=r"(a) : "l"(p));
    return a;
}
__device__ __forceinline__ void cp16(uint32_t dst, const void* src, int sz) {
    asm volatile("cp.async.cg.shared.global [%0], [%1], 16, %2;"
                 :: "r"(dst), "l"(src), "r"(sz) : "memory");
}

// ------------------------- kernel 1: gather frames + inline PE -> bf16 ----
__global__ void build_x(const float* __restrict__ sup, const float* __restrict__ qry) {
    long e = ((long)blockIdx.x * blockDim.x + threadIdx.x) * 8;
    if (e >= (long)NFRAMES * FEAT) return;
    int f = (int)(e / FEAT);
    int d = (int)(e % FEAT);
    int frame = f % SEQ;
    const float* src = (f < NS * SEQ) ? (sup + (long)f * FEAT + d)
                                      : (qry + (long)(f - NS * SEQ) * FEAT + d);
    float4 a = *(const float4*)src;
    float4 b = *(const float4*)(src + 4);
    float x[8] = {a.x, a.y, a.z, a.w, b.x, b.y, b.z, b.w};
    const float coef = -logf(10000.0f) / (float)FEAT;
    #pragma unroll
    for (int p = 0; p < 4; p++) {
        float div = __expf((float)(d + 2 * p) * coef);
        float s, c;
        __sincosf((float)frame * div, &s, &c);
        x[2 * p]     += s;
        x[2 * p + 1] += c;
    }
    __nv_bfloat162 h[4];
    #pragma unroll
    for (int p = 0; p < 4; p++) h[p] = __floats2bfloat162_rn(x[2 * p], x[2 * p + 1]);
    *(uint4*)(d_Xh + e) = *(uint4*)h;
}

// ------------------------- kernel 2: weight transpose -> bf16 -------------
__global__ void wtrans(const float* __restrict__ kw, const float* __restrict__ vw) {
    __shared__ float t[32][33];
    int p  = blockIdx.z;
    int n0 = blockIdx.x * 32, k0 = blockIdx.y * 32;
    const float* W = ((p < 2) ? kw : vw) + (size_t)((p & 1) * FEAT) * DOUT;
    #pragma unroll
    for (int i = 0; i < 4; i++) {
        int k = k0 + threadIdx.y + i * 8;
        t[threadIdx.y + i * 8][threadIdx.x] = W[(size_t)k * DOUT + n0 + threadIdx.x];
    }
    __syncthreads();
    #pragma unroll
    for (int i = 0; i < 4; i++) {
        int n = n0 + threadIdx.y + i * 8;
        d_WT[(size_t)(p * DOUT + n) * FEAT + k0 + threadIdx.x] =
            __float2bfloat16(t[threadIdx.x][threadIdx.y + i * 8]);
    }
}

// ------------------------- 128x256 projection GEMM (64x64 warp tiles) -----
#define PG_STRIDE 72
#define PG_ABYTES (128 * PG_STRIDE * 2)
#define PG_BBYTES (256 * PG_STRIDE * 2)
#define PG_STAGE  (PG_ABYTES + PG_BBYTES)
#define PG_SMEM   (3 * PG_STAGE)

__global__ void __launch_bounds__(256, 1) pgemm(const __nv_bfloat16* __restrict__ A,
                                                const __nv_bfloat16* __restrict__ B,
                                                __nv_bfloat16* __restrict__ C,
                                                int M, int N, int K,
                                                int lda, int ldb, int ldc)
{
    extern __shared__ __align__(16) char smem[];
    const uint32_t sbase = smem_u32(smem);
    const int tid  = threadIdx.x;
    const int wid  = tid >> 5, lane = tid & 31;
    const int wm   = wid >> 2, wn = wid & 3;
    const int m0   = blockIdx.y * 128, n0 = blockIdx.x * 256;
    const int nk   = K >> 6;

    float acc[4][8][4];
    #pragma unroll
    for (int i = 0; i < 4; i++)
        #pragma unroll
        for (int j = 0; j < 8; j++)
            #pragma unroll
            for (int r = 0; r < 4; r++) acc[i][j][r] = 0.f;

    const int ch = tid & 7;
    const int r0 = tid >> 3;
    bool vA[4], vB[8];
    const __nv_bfloat16 *pA[4], *pB[8];
    uint32_t dA[4], dB[8];
    #pragma unroll
    for (int g = 0; g < 4; g++) {
        int row = r0 + 32 * g;
        vA[g] = (m0 + row) < M;
        pA[g] = A + (size_t)(vA[g] ? m0 + row : 0) * lda + ch * 8;
        dA[g] = (uint32_t)(row * (PG_STRIDE * 2) + ch * 16);
    }
    #pragma unroll
    for (int g = 0; g < 8; g++) {
        int row = r0 + 32 * g;
        vB[g] = (n0 + row) < N;
        pB[g] = B + (size_t)(vB[g] ? n0 + row : 0) * ldb + ch * 8;
        dB[g] = (uint32_t)(row * (PG_STRIDE * 2) + ch * 16) + PG_ABYTES;
    }

    auto load_stage = [&](int sidx, int kc) {
        const int k0 = kc * 64;
        const uint32_t st = sbase + sidx * PG_STAGE;
        #pragma unroll
        for (int g = 0; g < 4; g++) cp16(st + dA[g], pA[g] + k0, vA[g] ? 16 : 0);
        #pragma unroll
        for (int g = 0; g < 8; g++) cp16(st + dB[g], pB[g] + k0, vB[g] ? 16 : 0);
        asm volatile("cp.async.commit_group;" ::: "memory");
    };

    uint32_t offA[4], offB[4];
    #pragma unroll
    for (int mt = 0; mt < 4; mt++)
        offA[mt] = (uint32_t)(((wm * 64 + mt * 16 + (lane & 15)) * PG_STRIDE
                               + (lane >> 4) * 8) * 2);
    #pragma unroll
    for (int nh = 0; nh < 4; nh++) {
        int nrow = wn * 64 + nh * 16 + ((lane >> 4) * 8) + (lane & 7);
        int kof  = ((lane >> 3) & 1) * 8;
        offB[nh] = (uint32_t)((nrow * PG_STRIDE + kof) * 2) + PG_ABYTES;
    }

    const int pst = nk < 2 ? nk : 2;
    for (int s = 0; s < pst; s++) load_stage(s, s);

    for (int i = 0; i < nk; i++) {
        if (i + 1 < nk) asm volatile("cp.async.wait_group 1;" ::: "memory");
        else            asm volatile("cp.async.wait_group 0;" ::: "memory");
        __syncthreads();

        if (i + 2 < nk) load_stage((i + 2) % 3, i + 2);

        const uint32_t stg = sbase + (i % 3) * PG_STAGE;

        #pragma unroll
        for (int ks = 0; ks < 4; ks++) {
            uint32_t a[4][4], b[8][2];
            #pragma unroll
            for (int nh = 0; nh < 4; nh++) {
                uint32_t addr = stg + offB[nh] + ks * 32;
                uint32_t q0, q1, q2, q3;
                asm volatile("ldmatrix.sync.aligned.m8n8.x4.shared.b16 {%0,%1,%2,%3}, [%4];"
                             : "=r"(q0), "=r"(q1), "=r"(q2), "=r"(q3) : "r"(addr));
                b[nh * 2][0] = q0;     b[nh * 2][1] = q1;
                b[nh * 2 + 1][0] = q2; b[nh * 2 + 1][1] = q3;
            }
            {
                uint32_t addr = stg + offA[0] + ks * 32;
                asm volatile("ldmatrix.sync.aligned.m8n8.x4.shared.b16 {%0,%1,%2,%3}, [%4];"
                             : "=r"(a[0][0]), "=r"(a[0][1]), "=r"(a[0][2]), "=r"(a[0][3])
                             : "r"(addr));
            }
            #pragma unroll
            for (int mt = 0; mt < 4; mt++) {
                if (mt < 3) {
                    uint32_t addr = stg + offA[mt + 1] + ks * 32;
                    asm volatile("ldmatrix.sync.aligned.m8n8.x4.shared.b16 {%0,%1,%2,%3}, [%4];"
                                 : "=r"(a[mt+1][0]), "=r"(a[mt+1][1]),
                                   "=r"(a[mt+1][2]), "=r"(a[mt+1][3])
                                 : "r"(addr));
                }
                #pragma unroll
                for (int nt = 0; nt < 8; nt++) {
                    asm volatile(
                        "mma.sync.aligned.m16n8k16.row.col.f32.bf16.bf16.f32 "
                        "{%0,%1,%2,%3}, {%4,%5,%6,%7}, {%8,%9}, {%0,%1,%2,%3};"
                        : "+f"(acc[mt][nt][0]), "+f"(acc[mt][nt][1]),
                          "+f"(acc[mt][nt][2]), "+f"(acc[mt][nt][3])
                        : "r"(a[mt][0]), "r"(a[mt][1]), "r"(a[mt][2]), "r"(a[mt][3]),
                          "r"(b[nt][0]), "r"(b[nt][1]));
                }
            }
        }
    }

    #pragma unroll
    for (int mt = 0; mt < 4; mt++) {
        #pragma unroll
        for (int nt = 0; nt < 8; nt++) {
            int mb = m0 + wm * 64 + mt * 16 + (lane >> 2);
            int nb = n0 + wn * 64 + nt * 8 + (lane & 3) * 2;
            if (nb >= N) continue;
            if (mb < M)
                *(__nv_bfloat162*)(C + (size_t)mb * ldc + nb) =
                    __floats2bfloat162_rn(acc[mt][nt][0], acc[mt][nt][1]);
            if (mb + 8 < M)
                *(__nv_bfloat162*)(C + (size_t)(mb + 8) * ldc + nb) =
                    __floats2bfloat162_rn(acc[mt][nt][2], acc[mt][nt][3]);
        }
    }
}

// ------------------------- bf16 mma.sync NT GEMM (batched, BK=64) ---------
// MODE 2: fused distance epilogue.  MODE 3: merged QK/QV/SS launch.
#define MG_STRIDE 72
#define MG_STAGE_B (128 * MG_STRIDE * 2)
#define MG_SMEM (3 * 2 * MG_STAGE_B)

struct BPtr { const __nv_bfloat16* A; const __nv_bfloat16* B; void* C; const float* Q; };
struct BatchArg { BPtr p[5]; };

template<int MODE>
__global__ void __launch_bounds__(256, 2) mgemm(BatchArg ba,
                                                int Ma, int Na, int Ka,
                                                int lda_a, int ldb_a, int ldc_a,
                                                float* __restrict__ Df)
{
    extern __shared__ __align__(16) char smem[];
    int m0, n0, M, N, K, lda, ldb, ldc;
    const __nv_bfloat16 *A, *B;
    void* Cv = nullptr;
    bool outbf;
    if (MODE == 3) {
        K = DOUT; lda = DOUT; ldb = DOUT;
        if (blockIdx.y < QYT) {
            const BPtr& bp = ba.p[blockIdx.z];
            A = bp.A; B = bp.B; Cv = bp.C;
            M = QROWS; N = SROWS; ldc = SROWS; outbf = false;
            m0 = blockIdx.y * 128; n0 = blockIdx.x * 128;
        } else {
            int idx = ((blockIdx.y - QYT) * 2 + blockIdx.z) * 6 + blockIdx.x;
            if (idx >= 20) return;
            int c = idx >> 2, sub = idx & 3;
            m0 = (sub >> 1) * 128; n0 = (sub & 1) * 128;
            A = ba.p[2].A + (size_t)c * CLS * DOUT;
            B = A;
            Cv = (void*)((__nv_bfloat16*)ba.p[2].C + (size_t)c * CLS * CPAD);
            M = CLS; N = CLS; ldc = CPAD; outbf = true;
        }
    } else {
        const BPtr& bp = ba.p[blockIdx.z];
        A = bp.A; B = bp.B; Cv = bp.C;
        M = Ma; N = Na; K = Ka; lda = lda_a; ldb = ldb_a; ldc = ldc_a;
        outbf = false;
        m0 = blockIdx.y * 128; n0 = blockIdx.x * 128;
    }

    const uint32_t sbase = smem_u32(smem);
    const int tid  = threadIdx.x;
    const int wid  = tid >> 5, lane = tid & 31;
    const int wm   = wid >> 2, wn = wid & 3;
    const int nk   = (K + 63) >> 6;

    float acc[4][4][4];
    #pragma unroll
    for (int i = 0; i < 4; i++)
        #pragma unroll
        for (int j = 0; j < 4; j++)
            #pragma unroll
            for (int r = 0; r < 4; r++) acc[i][j][r] = 0.f;

    const int ch = tid & 7;
    const int r0 = tid >> 3;
    bool vA[4], vB[4];
    const __nv_bfloat16 *pA[4], *pB[4];
    uint32_t dA[4], dB[4];
    #pragma unroll
    for (int g = 0; g < 4; g++) {
        int row = r0 + 32 * g;
        vA[g] = (m0 + row) < M;
        vB[g] = (n0 + row) < N;
        pA[g] = A + (size_t)(vA[g] ? m0 + row : 0) * lda + ch * 8;
        pB[g] = B + (size_t)(vB[g] ? n0 + row : 0) * ldb + ch * 8;
        dA[g] = (uint32_t)(row * (MG_STRIDE * 2) + ch * 16);
        dB[g] = dA[g] + MG_STAGE_B;
    }

    auto load_stage = [&](int sidx, int kc) {
        const int k0 = kc * 64;
        const uint32_t st = sbase + sidx * (2 * MG_STAGE_B);
        int szk;
        if (k0 + 64 <= K) szk = 16;
        else {
            int ke  = k0 + ch * 8;
            int rem = (K - ke) * 2;
            szk = rem >= 16 ? 16 : (rem > 0 ? rem : 0);
        }
        #pragma unroll
        for (int g = 0; g < 4; g++) {
            cp16(st + dA[g], pA[g] + k0, vA[g] ? szk : 0);
            cp16(st + dB[g], pB[g] + k0, vB[g] ? szk : 0);
        }
        asm volatile("cp.async.commit_group;" ::: "memory");
    };

    uint32_t offA[4], offB[2];
    #pragma unroll
    for (int mt = 0; mt < 4; mt++)
        offA[mt] = (uint32_t)(((wm * 64 + mt * 16 + (lane & 15)) * MG_STRIDE
                               + (lane >> 4) * 8) * 2);
    #pragma unroll
    for (int nh = 0; nh < 2; nh++) {
        int nrow = nh * 16 + ((lane >> 4) * 8) + (lane & 7);
        int kof  = ((lane >> 3) & 1) * 8;
        offB[nh] = (uint32_t)(((wn * 32 + nrow) * MG_STRIDE + kof) * 2) + MG_STAGE_B;
    }

    const int pst = nk < 2 ? nk : 2;
    for (int s = 0; s < pst; s++) load_stage(s, s);

    for (int i = 0; i < nk; i++) {
        if (i + 1 < nk) asm volatile("cp.async.wait_group 1;" ::: "memory");
        else            asm volatile("cp.async.wait_group 0;" ::: "memory");
        __syncthreads();

        if (i + 2 < nk) load_stage((i + 2) % 3, i + 2);

        const uint32_t stg = sbase + (i % 3) * (2 * MG_STAGE_B);

        #pragma unroll
        for (int ks = 0; ks < 4; ks++) {
            uint32_t a[4][4], b[4][2];
            #pragma unroll
            for (int nh = 0; nh < 2; nh++) {
                uint32_t addr = stg + offB[nh] + ks * 32;
                uint32_t q0, q1, q2, q3;
                asm volatile("ldmatrix.sync.aligned.m8n8.x4.shared.b16 {%0,%1,%2,%3}, [%4];"
                             : "=r"(q0), "=r"(q1), "=r"(q2), "=r"(q3) : "r"(addr));
                b[nh * 2][0] = q0;     b[nh * 2][1] = q1;
                b[nh * 2 + 1][0] = q2; b[nh * 2 + 1][1] = q3;
            }
            {
                uint32_t addr = stg + offA[0] + ks * 32;
                asm volatile("ldmatrix.sync.aligned.m8n8.x4.shared.b16 {%0,%1,%2,%3}, [%4];"
                             : "=r"(a[0][0]), "=r"(a[0][1]), "=r"(a[0][2]), "=r"(a[0][3])
                             : "r"(addr));
            }
            #pragma unroll
            for (int mt = 0; mt < 4; mt++) {
                if (mt < 3) {
                    uint32_t addr = stg + offA[mt + 1] + ks * 32;
                    asm volatile("ldmatrix.sync.aligned.m8n8.x4.shared.b16 {%0,%1,%2,%3}, [%4];"
                                 : "=r"(a[mt+1][0]), "=r"(a[mt+1][1]),
                                   "=r"(a[mt+1][2]), "=r"(a[mt+1][3])
                                 : "r"(addr));
                }
                #pragma unroll
                for (int nt = 0; nt < 4; nt++) {
                    asm volatile(
                        "mma.sync.aligned.m16n8k16.row.col.f32.bf16.bf16.f32 "
                        "{%0,%1,%2,%3}, {%4,%5,%6,%7}, {%8,%9}, {%0,%1,%2,%3};"
                        : "+f"(acc[mt][nt][0]), "+f"(acc[mt][nt][1]),
                          "+f"(acc[mt][nt][2]), "+f"(acc[mt][nt][3])
                        : "r"(a[mt][0]), "r"(a[mt][1]), "r"(a[mt][2]), "r"(a[mt][3]),
                          "r"(b[nt][0]), "r"(b[nt][1]));
                }
            }
        }
    }

    if (MODE == 2) {
        const float* __restrict__ Q = ba.p[blockIdx.z].Q;
        float* Dz = Df + (size_t)blockIdx.z * (size_t)M * 8;
        #pragma unroll
        for (int mt = 0; mt < 4; mt++) {
            #pragma unroll
            for (int r = 0; r < 2; r++) {
                int m = m0 + wm * 64 + mt * 16 + (lane >> 2) + r * 8;
                float p = 0.f;
                if (m < M) {
                    #pragma unroll
                    for (int nt = 0; nt < 4; nt++) {
                        int nb = n0 + wn * 32 + nt * 8 + (lane & 3) * 2;
                        if (nb < N) {
                            float at0 = __bfloat162float(A[(size_t)m * lda + nb]);
                            p += at0 * (acc[mt][nt][r * 2] - 2.f * Q[(size_t)m * ldc + nb]);
                            if (nb + 1 < N) {
                                float at1 = __bfloat162float(A[(size_t)m * lda + nb + 1]);
                                p += at1 * (acc[mt][nt][r * 2 + 1] - 2.f * Q[(size_t)m * ldc + nb + 1]);
                            }
                        }
                    }
                }
                p += __shfl_xor_sync(0xffffffffu, p, 1);
                p += __shfl_xor_sync(0xffffffffu, p, 2);
                if (m < M && (lane & 3) == 0)
                    Dz[(size_t)m * 8 + blockIdx.x * 4 + wn] = p;
            }
        }
        return;
    }

    #pragma unroll
    for (int mt = 0; mt < 4; mt++) {
        #pragma unroll
        for (int nt = 0; nt < 4; nt++) {
            int mb = m0 + wm * 64 + mt * 16 + (lane >> 2);
            int nb = n0 + wn * 32 + nt * 8 + (lane & 3) * 2;
            if (nb >= N) continue;
            if (outbf) {
                __nv_bfloat16* C = (__nv_bfloat16*)Cv;
                if (mb < M)
                    *(__nv_bfloat162*)(C + (size_t)mb * ldc + nb) =
                        __floats2bfloat162_rn(acc[mt][nt][0], acc[mt][nt][1]);
                if (mb + 8 < M)
                    *(__nv_bfloat162*)(C + (size_t)(mb + 8) * ldc + nb) =
                        __floats2bfloat162_rn(acc[mt][nt][2], acc[mt][nt][3]);
            } else {
                float* C = (float*)Cv;
                if (mb < M)
                    *(float2*)(C + (size_t)mb * ldc + nb) =
                        make_float2(acc[mt][nt][0], acc[mt][nt][1]);
                if (mb + 8 < M)
                    *(float2*)(C + (size_t)(mb + 8) * ldc + nb) =
                        make_float2(acc[mt][nt][2], acc[mt][nt][3]);
            }
        }
    }
}

// ------------------------- kernel 3: row-level assemble (L2 direct) -------
// One warp per tuple-row; reads the two frame rows straight from L2-resident
// Ph. Identical per-warp arithmetic order to the staged version.
__global__ void __launch_bounds__(256) assemble(const float* __restrict__ k_b,
                                                const float* __restrict__ v_b,
                                                const float* __restrict__ gamma,
                                                const float* __restrict__ beta)
{
    int rb = blockIdx.x * 8 + (threadIdx.x >> 5);
    if (rb >= NROWS) return;
    int lane = threadIdx.x & 31;

    int clip, w;
    if (rb < SROWS) { clip = rb / TLEN;              w = rb % TLEN; }
    else { int qr = rb - SROWS; clip = NS + qr / TLEN; w = qr % TLEN; }
    int fa = clip * SEQ + c_TA[w];
    int fb = clip * SEQ + c_TB[w];

    const __nv_bfloat162* A2 = (const __nv_bfloat162*)(d_Ph + (size_t)fa * WSTK);
    const __nv_bfloat162* B2 = (const __nv_bfloat162*)(d_Ph + (size_t)fb * WSTK);
    const float2* kb2 = (const float2*)k_b;
    const float2* vb2 = (const float2*)v_b;
    __nv_bfloat162* vout = (__nv_bfloat162*)(d_VSh + (size_t)rb * DOUT);

    float s1 = 0.f, s2 = 0.f, vn = 0.f;
    #pragma unroll 6
    for (int i = 0; i < 18; i++) {
        int j2 = lane + 32 * i;
        __nv_bfloat162 ka = A2[j2];
        __nv_bfloat162 kb = B2[DOUT / 2 + j2];
        float2 kbias = kb2[j2];
        float k0 = __low2float(ka)  + __low2float(kb)  + kbias.x;
        float k1 = __high2float(ka) + __high2float(kb) + kbias.y;
        s1 += k0 + k1; s2 += k0 * k0 + k1 * k1;
        __nv_bfloat162 va = A2[DOUT + j2];
        __nv_bfloat162 vb = B2[3 * DOUT / 2 + j2];
        float2 vbias = vb2[j2];
        float v0 = __low2float(va)  + __low2float(vb)  + vbias.x;
        float v1 = __high2float(va) + __high2float(vb) + vbias.y;
        vn += v0 * v0 + v1 * v1;
        vout[j2] = __floats2bfloat162_rn(v0, v1);
    }
    #pragma unroll
    for (int s = 16; s > 0; s >>= 1) {
        s1 += __shfl_xor_sync(0xffffffffu, s1, s);
        s2 += __shfl_xor_sync(0xffffffffu, s2, s);
        vn += __shfl_xor_sync(0xffffffffu, vn, s);
    }
    float mu  = s1 / (float)DOUT;
    float var = s2 / (float)DOUT - mu * mu;
    float inv = rsqrtf(var + LN_EPS);

    const float2* g2 = (const float2*)gamma;
    const float2* b2 = (const float2*)beta;
    __nv_bfloat162* kout = (__nv_bfloat162*)(d_KSh + (size_t)rb * DOUT);
    #pragma unroll 6
    for (int i = 0; i < 18; i++) {
        int j2 = lane + 32 * i;
        __nv_bfloat162 ka = A2[j2];
        __nv_bfloat162 kb = B2[DOUT / 2 + j2];
        float2 kbias = kb2[j2];
        float k0 = __low2float(ka)  + __low2float(kb)  + kbias.x;
        float k1 = __high2float(ka) + __high2float(kb) + kbias.y;
        float2 g = g2[j2], bt = b2[j2];
        kout[j2] = __floats2bfloat162_rn((k0 - mu) * inv * g.x + bt.x,
                                         (k1 - mu) * inv * g.y + bt.y);
    }
    if (lane == 0) d_VN[rb] = vn;
}

// ------------------------- kernel 4: softmax (bf16 out only) --------------
__global__ void softmax_k(float scale) {
    int row  = blockIdx.x;
    int c    = threadIdx.x >> 5;
    int lane = threadIdx.x & 31;
    const float* p = d_QK + (size_t)row * SROWS + c * CLS;
    __nv_bfloat16* pb = d_Ab + (size_t)row * ABLD + c * CPAD;

    float v[5];
    float mx = -1e30f;
    #pragma unroll
    for (int i = 0; i < 5; i++) {
        int j = lane + 32 * i;
        v[i] = (j < CLS) ? p[j] * scale : -1e30f;
        mx = fmaxf(mx, v[i]);
    }
    #pragma unroll
    for (int s = 16; s > 0; s >>= 1) mx = fmaxf(mx, __shfl_xor_sync(0xffffffffu, mx, s));
    float sum = 0.f;
    #pragma unroll
    for (int i = 0; i < 5; i++) {
        int j = lane + 32 * i;
        if (j < CLS) { v[i] = expf(v[i] - mx); sum += v[i]; }
    }
    #pragma unroll
    for (int s = 16; s > 0; s >>= 1) sum += __shfl_xor_sync(0xffffffffu, sum, s);
    float invs = 1.0f / sum;
    #pragma unroll
    for (int i = 0; i < 5; i++) {
        int j = lane + 32 * i;
        if (j < CLS) pb[j] = __float2bfloat16(v[i] * invs);
    }
}

// ------------------------- kernel 5: tiny final reduction -----------------
__global__ void final_k(const float* __restrict__ gt, const float* __restrict__ tw,
                        float* __restrict__ out)
{
    int q = blockIdx.x;
    int c = threadIdx.x >> 5;
    int lane = threadIdx.x & 31;
    float temp = gt[0] * tw[0];

    float tot = 0.f;
    if (lane < TLEN) {
        tot = d_VN[SROWS + q * TLEN + lane];
        const float* dd = d_D2 + ((size_t)c * QROWS + q * TLEN + lane) * 8;
        float4 x = *(const float4*)dd;
        float4 y = *(const float4*)(dd + 4);
        tot += x.x + x.y + x.z + x.w + y.x + y.y + y.z + y.w;
    }
    #pragma unroll
    for (int s = 16; s > 0; s >>= 1) tot += __shfl_xor_sync(0xffffffffu, tot, s);
    if (lane == 0) out[q * WAY + c] = -(tot / (float)TLEN) * temp;
}

// ------------------------- launch -----------------------------------------
extern "C" void kernel_launch(void* const* d_in, const int* in_sizes, int n_in,
                              void* d_out, int out_size) {
    const float* sup   = (const float*)d_in[0];
    const float* qry   = (const float*)d_in[2];
    const float* k_w   = (const float*)d_in[3];
    const float* k_b   = (const float*)d_in[4];
    const float* v_w   = (const float*)d_in[5];
    const float* v_b   = (const float*)d_in[6];
    const float* gamma = (const float*)d_in[7];
    const float* beta  = (const float*)d_in[8];
    const float* gt    = (const float*)d_in[9];
    const float* tw    = (const float*)d_in[10];
    float* out = (float*)d_out;

    __nv_bfloat16 *pXh, *pWT, *pPh, *pKSh, *pVSh, *pAb, *pSSh;
    float *pQK, *pQV, *pD2;
    cudaGetSymbolAddress((void**)&pXh,  d_Xh);
    cudaGetSymbolAddress((void**)&pWT,  d_WT);
    cudaGetSymbolAddress((void**)&pPh,  d_Ph);
    cudaGetSymbolAddress((void**)&pKSh, d_KSh);
    cudaGetSymbolAddress((void**)&pVSh, d_VSh);
    cudaGetSymbolAddress((void**)&pQK,  d_QK);
    cudaGetSymbolAddress((void**)&pQV,  d_QV);
    cudaGetSymbolAddress((void**)&pD2,  d_D2);
    cudaGetSymbolAddress((void**)&pAb,  d_Ab);
    cudaGetSymbolAddress((void**)&pSSh, d_SSh);

    cudaFuncSetAttribute(pgemm,    cudaFuncAttributeMaxDynamicSharedMemorySize, PG_SMEM);
    cudaFuncSetAttribute(mgemm<2>, cudaFuncAttributeMaxDynamicSharedMemorySize, MG_SMEM);
    cudaFuncSetAttribute(mgemm<3>, cudaFuncAttributeMaxDynamicSharedMemorySize, MG_SMEM);

    build_x<<<(NFRAMES * FEAT / 8 + 255) / 256, 256>>>(sup, qry);
    wtrans<<<dim3(DOUT / 32, FEAT / 32, 4), dim3(32, 8)>>>(k_w, v_w);

    // Projections (bf16 out): Ph[4200, 4608] = Xh @ WT^T  (128x256 tiles)
    {
        dim3 g((WSTK + 255) / 256, (NFRAMES + 127) / 128);
        pgemm<<<g, 256, PG_SMEM>>>(pXh, pWT, pPh, NFRAMES, WSTK, FEAT, FEAT, FEAT, WSTK);
    }

    assemble<<<(NROWS + 7) / 8, 256>>>(k_b, v_b, gamma, beta);

    // Merged QK + QV + per-class SS Gram (grid (6, 112, 2))
    {
        BatchArg ba = {};
        ba.p[0] = { pKSh + (size_t)SROWS * DOUT, pKSh, (void*)pQK, nullptr };
        ba.p[1] = { pVSh + (size_t)SROWS * DOUT, pVSh, (void*)pQV, nullptr };
        ba.p[2] = { pVSh, nullptr, (void*)pSSh, nullptr };
        dim3 g(6, QYT + 2, 2);
        mgemm<3><<<g, 256, MG_SMEM>>>(ba, 0, 0, 0, 0, 0, 0, nullptr);
    }

    softmax_k<<<QROWS, 160>>>(1.0f / sqrtf((float)DOUT));

    // Fused H + distance partials (z=5)
    {
        BatchArg ba = {};
        for (int c = 0; c < WAY; c++)
            ba.p[c] = { pAb + (size_t)c * CPAD,
                        pSSh + (size_t)c * CLS * CPAD,
                        nullptr,
                        pQV + (size_t)c * CLS };
        dim3 g((CLS + 127) / 128, (QROWS + 127) / 128, WAY);
        mgemm<2><<<g, 256, MG_SMEM>>>(ba, QROWS, CLS, CLS, ABLD, CPAD, SROWS, pD2);
    }

    final_k<<<NQ, 160>>>(gt, tw, out);
}

// round 15
// speedup vs baseline: 1.0557x; 1.0269x over previous
#include <cuda_runtime.h>
#include <cuda_bf16.h>
#include <math.h>
#include <stdint.h>

#define SEQ 8
#define FEAT 2048
#define TLEN 28
#define DOUT 1152
#define WAY 5
#define SHOT 5
#define NQ 500
#define NS 25
#define CLIPS (NS + NQ)                /* 525 */
#define NFRAMES (CLIPS * SEQ)          /* 4200 */
#define NROWS (CLIPS * TLEN)           /* 14700 */
#define SROWS (NS * TLEN)              /* 700 */
#define QROWS (NQ * TLEN)              /* 14000 */
#define CLS 140                        /* SHOT*TLEN */
#define LN_EPS 1e-5f
#define WSTK (4 * DOUT)                /* 4608 */
#define ABLD 720                       /* bf16 attn row stride (5*144) */
#define CPAD 144                       /* padded class block stride */
#define QYT 110                        /* QROWS m-tiles */

// ------------------------- scratch (device globals) -----------------------
__device__ __nv_bfloat16  d_Xh [NFRAMES * FEAT];
__device__ __nv_bfloat16  d_WT [WSTK * FEAT];
__device__ __nv_bfloat16  d_Ph [NFRAMES * WSTK];
__device__ __nv_bfloat16  d_KSh[NROWS * DOUT];
__device__ __nv_bfloat16  d_VSh[NROWS * DOUT];
__device__ float          d_VN [NROWS];
__device__ float          d_QK [QROWS * SROWS];           // raw scores (fp32)
__device__ __nv_bfloat16  d_Ab [QROWS * ABLD];            // attn bf16, padded blocks
__device__ float          d_QV [QROWS * SROWS];
__device__ float          d_D2 [WAY * QROWS * 8];         // fused distance partials
__device__ __nv_bfloat16  d_SSh[WAY * CLS * CPAD];

__constant__ int c_TA[TLEN] = {0,0,0,0,0,0,0,1,1,1,1,1,1,2,2,2,2,2,3,3,3,3,4,4,4,5,5,6};
__constant__ int c_TB[TLEN] = {1,2,3,4,5,6,7,2,3,4,5,6,7,3,4,5,6,7,4,5,6,7,5,6,7,6,7,7};

__device__ __forceinline__ uint32_t smem_u32(const void* p) {
    uint32_t a;
    asm("{ .reg .u64 t; cvta.to.shared.u64 t, %1; cvt.u32.u64 %0, t; }" : "=r"(a) : "l"(p));
    return a;
}
__device__ __forceinline__ void cp16(uint32_t dst, const void* src, int sz) {
    asm volatile("cp.async.cg.shared.global [%0], [%1], 16, %2;"
                 :: "r"(dst), "l"(src), "r"(sz) : "memory");
}

// ------------------------- kernel 1: gather frames + inline PE -> bf16 ----
__global__ void build_x(const float* __restrict__ sup, const float* __restrict__ qry) {
    long e = ((long)blockIdx.x * blockDim.x + threadIdx.x) * 8;
    if (e >= (long)NFRAMES * FEAT) return;
    int f = (int)(e / FEAT);
    int d = (int)(e % FEAT);
    int frame = f % SEQ;
    const float* src = (f < NS * SEQ) ? (sup + (long)f * FEAT + d)
                                      : (qry + (long)(f - NS * SEQ) * FEAT + d);
    float4 a = *(const float4*)src;
    float4 b = *(const float4*)(src + 4);
    float x[8] = {a.x, a.y, a.z, a.w, b.x, b.y, b.z, b.w};
    const float coef = -logf(10000.0f) / (float)FEAT;
    #pragma unroll
    for (int p = 0; p < 4; p++) {
        float div = __expf((float)(d + 2 * p) * coef);
        float s, c;
        __sincosf((float)frame * div, &s, &c);
        x[2 * p]     += s;
        x[2 * p + 1] += c;
    }
    __nv_bfloat162 h[4];
    #pragma unroll
    for (int p = 0; p < 4; p++) h[p] = __floats2bfloat162_rn(x[2 * p], x[2 * p + 1]);
    *(uint4*)(d_Xh + e) = *(uint4*)h;
}

// ------------------------- kernel 2: weight transpose -> bf16 -------------
__global__ void wtrans(const float* __restrict__ kw, const float* __restrict__ vw) {
    __shared__ float t[32][33];
    int p  = blockIdx.z;
    int n0 = blockIdx.x * 32, k0 = blockIdx.y * 32;
    const float* W = ((p < 2) ? kw : vw) + (size_t)((p & 1) * FEAT) * DOUT;
    #pragma unroll
    for (int i = 0; i < 4; i++) {
        int k = k0 + threadIdx.y + i * 8;
        t[threadIdx.y + i * 8][threadIdx.x] = W[(size_t)k * DOUT + n0 + threadIdx.x];
    }
    __syncthreads();
    #pragma unroll
    for (int i = 0; i < 4; i++) {
        int n = n0 + threadIdx.y + i * 8;
        d_WT[(size_t)(p * DOUT + n) * FEAT + k0 + threadIdx.x] =
            __float2bfloat16(t[threadIdx.x][threadIdx.y + i * 8]);
    }
}

// ------------------------- 128x256 projection GEMM (64x64 warp tiles) -----
#define PG_STRIDE 72
#define PG_ABYTES (128 * PG_STRIDE * 2)
#define PG_BBYTES (256 * PG_STRIDE * 2)
#define PG_STAGE  (PG_ABYTES + PG_BBYTES)
#define PG_SMEM   (3 * PG_STAGE)

__global__ void __launch_bounds__(256, 1) pgemm(const __nv_bfloat16* __restrict__ A,
                                                const __nv_bfloat16* __restrict__ B,
                                                __nv_bfloat16* __restrict__ C,
                                                int M, int N, int K,
                                                int lda, int ldb, int ldc)
{
    extern __shared__ __align__(16) char smem[];
    const uint32_t sbase = smem_u32(smem);
    const int tid  = threadIdx.x;
    const int wid  = tid >> 5, lane = tid & 31;
    const int wm   = wid >> 2, wn = wid & 3;
    const int m0   = blockIdx.y * 128, n0 = blockIdx.x * 256;
    const int nk   = K >> 6;

    float acc[4][8][4];
    #pragma unroll
    for (int i = 0; i < 4; i++)
        #pragma unroll
        for (int j = 0; j < 8; j++)
            #pragma unroll
            for (int r = 0; r < 4; r++) acc[i][j][r] = 0.f;

    const int ch = tid & 7;
    const int r0 = tid >> 3;
    bool vA[4], vB[8];
    const __nv_bfloat16 *pA[4], *pB[8];
    uint32_t dA[4], dB[8];
    #pragma unroll
    for (int g = 0; g < 4; g++) {
        int row = r0 + 32 * g;
        vA[g] = (m0 + row) < M;
        pA[g] = A + (size_t)(vA[g] ? m0 + row : 0) * lda + ch * 8;
        dA[g] = (uint32_t)(row * (PG_STRIDE * 2) + ch * 16);
    }
    #pragma unroll
    for (int g = 0; g < 8; g++) {
        int row = r0 + 32 * g;
        vB[g] = (n0 + row) < N;
        pB[g] = B + (size_t)(vB[g] ? n0 + row : 0) * ldb + ch * 8;
        dB[g] = (uint32_t)(row * (PG_STRIDE * 2) + ch * 16) + PG_ABYTES;
    }

    auto load_stage = [&](int sidx, int kc) {
        const int k0 = kc * 64;
        const uint32_t st = sbase + sidx * PG_STAGE;
        #pragma unroll
        for (int g = 0; g < 4; g++) cp16(st + dA[g], pA[g] + k0, vA[g] ? 16 : 0);
        #pragma unroll
        for (int g = 0; g < 8; g++) cp16(st + dB[g], pB[g] + k0, vB[g] ? 16 : 0);
        asm volatile("cp.async.commit_group;" ::: "memory");
    };

    uint32_t offA[4], offB[4];
    #pragma unroll
    for (int mt = 0; mt < 4; mt++)
        offA[mt] = (uint32_t)(((wm * 64 + mt * 16 + (lane & 15)) * PG_STRIDE
                               + (lane >> 4) * 8) * 2);
    #pragma unroll
    for (int nh = 0; nh < 4; nh++) {
        int nrow = wn * 64 + nh * 16 + ((lane >> 4) * 8) + (lane & 7);
        int kof  = ((lane >> 3) & 1) * 8;
        offB[nh] = (uint32_t)((nrow * PG_STRIDE + kof) * 2) + PG_ABYTES;
    }

    const int pst = nk < 2 ? nk : 2;
    for (int s = 0; s < pst; s++) load_stage(s, s);

    for (int i = 0; i < nk; i++) {
        if (i + 1 < nk) asm volatile("cp.async.wait_group 1;" ::: "memory");
        else            asm volatile("cp.async.wait_group 0;" ::: "memory");
        __syncthreads();

        if (i + 2 < nk) load_stage((i + 2) % 3, i + 2);

        const uint32_t stg = sbase + (i % 3) * PG_STAGE;

        #pragma unroll
        for (int ks = 0; ks < 4; ks++) {
            uint32_t a[4][4], b[8][2];
            #pragma unroll
            for (int nh = 0; nh < 4; nh++) {
                uint32_t addr = stg + offB[nh] + ks * 32;
                uint32_t q0, q1, q2, q3;
                asm volatile("ldmatrix.sync.aligned.m8n8.x4.shared.b16 {%0,%1,%2,%3}, [%4];"
                             : "=r"(q0), "=r"(q1), "=r"(q2), "=r"(q3) : "r"(addr));
                b[nh * 2][0] = q0;     b[nh * 2][1] = q1;
                b[nh * 2 + 1][0] = q2; b[nh * 2 + 1][1] = q3;
            }
            {
                uint32_t addr = stg + offA[0] + ks * 32;
                asm volatile("ldmatrix.sync.aligned.m8n8.x4.shared.b16 {%0,%1,%2,%3}, [%4];"
                             : "=r"(a[0][0]), "=r"(a[0][1]), "=r"(a[0][2]), "=r"(a[0][3])
                             : "r"(addr));
            }
            #pragma unroll
            for (int mt = 0; mt < 4; mt++) {
                if (mt < 3) {
                    uint32_t addr = stg + offA[mt + 1] + ks * 32;
                    asm volatile("ldmatrix.sync.aligned.m8n8.x4.shared.b16 {%0,%1,%2,%3}, [%4];"
                                 : "=r"(a[mt+1][0]), "=r"(a[mt+1][1]),
                                   "=r"(a[mt+1][2]), "=r"(a[mt+1][3])
                                 : "r"(addr));
                }
                #pragma unroll
                for (int nt = 0; nt < 8; nt++) {
                    asm volatile(
                        "mma.sync.aligned.m16n8k16.row.col.f32.bf16.bf16.f32 "
                        "{%0,%1,%2,%3}, {%4,%5,%6,%7}, {%8,%9}, {%0,%1,%2,%3};"
                        : "+f"(acc[mt][nt][0]), "+f"(acc[mt][nt][1]),
                          "+f"(acc[mt][nt][2]), "+f"(acc[mt][nt][3])
                        : "r"(a[mt][0]), "r"(a[mt][1]), "r"(a[mt][2]), "r"(a[mt][3]),
                          "r"(b[nt][0]), "r"(b[nt][1]));
                }
            }
        }
    }

    #pragma unroll
    for (int mt = 0; mt < 4; mt++) {
        #pragma unroll
        for (int nt = 0; nt < 8; nt++) {
            int mb = m0 + wm * 64 + mt * 16 + (lane >> 2);
            int nb = n0 + wn * 64 + nt * 8 + (lane & 3) * 2;
            if (nb >= N) continue;
            if (mb < M)
                *(__nv_bfloat162*)(C + (size_t)mb * ldc + nb) =
                    __floats2bfloat162_rn(acc[mt][nt][0], acc[mt][nt][1]);
            if (mb + 8 < M)
                *(__nv_bfloat162*)(C + (size_t)(mb + 8) * ldc + nb) =
                    __floats2bfloat162_rn(acc[mt][nt][2], acc[mt][nt][3]);
        }
    }
}

// ------------------------- bf16 mma.sync NT GEMM (batched, BK=64) ---------
// MODE 2: fused distance epilogue.  MODE 3: merged QK/QV/SS launch.
#define MG_STRIDE 72
#define MG_STAGE_B (128 * MG_STRIDE * 2)
#define MG_SMEM (3 * 2 * MG_STAGE_B)

struct BPtr { const __nv_bfloat16* A; const __nv_bfloat16* B; void* C; const float* Q; };
struct BatchArg { BPtr p[5]; };

template<int MODE>
__global__ void __launch_bounds__(256, 2) mgemm(BatchArg ba,
                                                int Ma, int Na, int Ka,
                                                int lda_a, int ldb_a, int ldc_a,
                                                float* __restrict__ Df)
{
    extern __shared__ __align__(16) char smem[];
    int m0, n0, M, N, K, lda, ldb, ldc;
    const __nv_bfloat16 *A, *B;
    void* Cv = nullptr;
    bool outbf;
    if (MODE == 3) {
        K = DOUT; lda = DOUT; ldb = DOUT;
        if (blockIdx.y < QYT) {
            const BPtr& bp = ba.p[blockIdx.z];
            A = bp.A; B = bp.B; Cv = bp.C;
            M = QROWS; N = SROWS; ldc = SROWS; outbf = false;
            m0 = blockIdx.y * 128; n0 = blockIdx.x * 128;
        } else {
            int idx = ((blockIdx.y - QYT) * 2 + blockIdx.z) * 6 + blockIdx.x;
            if (idx >= 20) return;
            int c = idx >> 2, sub = idx & 3;
            m0 = (sub >> 1) * 128; n0 = (sub & 1) * 128;
            A = ba.p[2].A + (size_t)c * CLS * DOUT;
            B = A;
            Cv = (void*)((__nv_bfloat16*)ba.p[2].C + (size_t)c * CLS * CPAD);
            M = CLS; N = CLS; ldc = CPAD; outbf = true;
        }
    } else {
        const BPtr& bp = ba.p[blockIdx.z];
        A = bp.A; B = bp.B; Cv = bp.C;
        M = Ma; N = Na; K = Ka; lda = lda_a; ldb = ldb_a; ldc = ldc_a;
        outbf = false;
        m0 = blockIdx.y * 128; n0 = blockIdx.x * 128;
    }

    const uint32_t sbase = smem_u32(smem);
    const int tid  = threadIdx.x;
    const int wid  = tid >> 5, lane = tid & 31;
    const int wm   = wid >> 2, wn = wid & 3;
    const int nk   = (K + 63) >> 6;

    float acc[4][4][4];
    #pragma unroll
    for (int i = 0; i < 4; i++)
        #pragma unroll
        for (int j = 0; j < 4; j++)
            #pragma unroll
            for (int r = 0; r < 4; r++) acc[i][j][r] = 0.f;

    const int ch = tid & 7;
    const int r0 = tid >> 3;
    bool vA[4], vB[4];
    const __nv_bfloat16 *pA[4], *pB[4];
    uint32_t dA[4], dB[4];
    #pragma unroll
    for (int g = 0; g < 4; g++) {
        int row = r0 + 32 * g;
        vA[g] = (m0 + row) < M;
        vB[g] = (n0 + row) < N;
        pA[g] = A + (size_t)(vA[g] ? m0 + row : 0) * lda + ch * 8;
        pB[g] = B + (size_t)(vB[g] ? n0 + row : 0) * ldb + ch * 8;
        dA[g] = (uint32_t)(row * (MG_STRIDE * 2) + ch * 16);
        dB[g] = dA[g] + MG_STAGE_B;
    }

    auto load_stage = [&](int sidx, int kc) {
        const int k0 = kc * 64;
        const uint32_t st = sbase + sidx * (2 * MG_STAGE_B);
        int szk;
        if (k0 + 64 <= K) szk = 16;
        else {
            int ke  = k0 + ch * 8;
            int rem = (K - ke) * 2;
            szk = rem >= 16 ? 16 : (rem > 0 ? rem : 0);
        }
        #pragma unroll
        for (int g = 0; g < 4; g++) {
            cp16(st + dA[g], pA[g] + k0, vA[g] ? szk : 0);
            cp16(st + dB[g], pB[g] + k0, vB[g] ? szk : 0);
        }
        asm volatile("cp.async.commit_group;" ::: "memory");
    };

    uint32_t offA[4], offB[2];
    #pragma unroll
    for (int mt = 0; mt < 4; mt++)
        offA[mt] = (uint32_t)(((wm * 64 + mt * 16 + (lane & 15)) * MG_STRIDE
                               + (lane >> 4) * 8) * 2);
    #pragma unroll
    for (int nh = 0; nh < 2; nh++) {
        int nrow = nh * 16 + ((lane >> 4) * 8) + (lane & 7);
        int kof  = ((lane >> 3) & 1) * 8;
        offB[nh] = (uint32_t)(((wn * 32 + nrow) * MG_STRIDE + kof) * 2) + MG_STAGE_B;
    }

    const int pst = nk < 2 ? nk : 2;
    for (int s = 0; s < pst; s++) load_stage(s, s);

    for (int i = 0; i < nk; i++) {
        if (i + 1 < nk) asm volatile("cp.async.wait_group 1;" ::: "memory");
        else            asm volatile("cp.async.wait_group 0;" ::: "memory");
        __syncthreads();

        if (i + 2 < nk) load_stage((i + 2) % 3, i + 2);

        const uint32_t stg = sbase + (i % 3) * (2 * MG_STAGE_B);

        #pragma unroll
        for (int ks = 0; ks < 4; ks++) {
            uint32_t a[4][4], b[4][2];
            #pragma unroll
            for (int nh = 0; nh < 2; nh++) {
                uint32_t addr = stg + offB[nh] + ks * 32;
                uint32_t q0, q1, q2, q3;
                asm volatile("ldmatrix.sync.aligned.m8n8.x4.shared.b16 {%0,%1,%2,%3}, [%4];"
                             : "=r"(q0), "=r"(q1), "=r"(q2), "=r"(q3) : "r"(addr));
                b[nh * 2][0] = q0;     b[nh * 2][1] = q1;
                b[nh * 2 + 1][0] = q2; b[nh * 2 + 1][1] = q3;
            }
            {
                uint32_t addr = stg + offA[0] + ks * 32;
                asm volatile("ldmatrix.sync.aligned.m8n8.x4.shared.b16 {%0,%1,%2,%3}, [%4];"
                             : "=r"(a[0][0]), "=r"(a[0][1]), "=r"(a[0][2]), "=r"(a[0][3])
                             : "r"(addr));
            }
            #pragma unroll
            for (int mt = 0; mt < 4; mt++) {
                if (mt < 3) {
                    uint32_t addr = stg + offA[mt + 1] + ks * 32;
                    asm volatile("ldmatrix.sync.aligned.m8n8.x4.shared.b16 {%0,%1,%2,%3}, [%4];"
                                 : "=r"(a[mt+1][0]), "=r"(a[mt+1][1]),
                                   "=r"(a[mt+1][2]), "=r"(a[mt+1][3])
                                 : "r"(addr));
                }
                #pragma unroll
                for (int nt = 0; nt < 4; nt++) {
                    asm volatile(
                        "mma.sync.aligned.m16n8k16.row.col.f32.bf16.bf16.f32 "
                        "{%0,%1,%2,%3}, {%4,%5,%6,%7}, {%8,%9}, {%0,%1,%2,%3};"
                        : "+f"(acc[mt][nt][0]), "+f"(acc[mt][nt][1]),
                          "+f"(acc[mt][nt][2]), "+f"(acc[mt][nt][3])
                        : "r"(a[mt][0]), "r"(a[mt][1]), "r"(a[mt][2]), "r"(a[mt][3]),
                          "r"(b[nt][0]), "r"(b[nt][1]));
                }
            }
        }
    }

    if (MODE == 2) {
        const float* __restrict__ Q = ba.p[blockIdx.z].Q;
        float* Dz = Df + (size_t)blockIdx.z * (size_t)M * 8;
        #pragma unroll
        for (int mt = 0; mt < 4; mt++) {
            #pragma unroll
            for (int r = 0; r < 2; r++) {
                int m = m0 + wm * 64 + mt * 16 + (lane >> 2) + r * 8;
                float p = 0.f;
                if (m < M) {
                    #pragma unroll
                    for (int nt = 0; nt < 4; nt++) {
                        int nb = n0 + wn * 32 + nt * 8 + (lane & 3) * 2;
                        if (nb < N) {
                            float at0 = __bfloat162float(A[(size_t)m * lda + nb]);
                            p += at0 * (acc[mt][nt][r * 2] - 2.f * Q[(size_t)m * ldc + nb]);
                            if (nb + 1 < N) {
                                float at1 = __bfloat162float(A[(size_t)m * lda + nb + 1]);
                                p += at1 * (acc[mt][nt][r * 2 + 1] - 2.f * Q[(size_t)m * ldc + nb + 1]);
                            }
                        }
                    }
                }
                p += __shfl_xor_sync(0xffffffffu, p, 1);
                p += __shfl_xor_sync(0xffffffffu, p, 2);
                if (m < M && (lane & 3) == 0)
                    Dz[(size_t)m * 8 + blockIdx.x * 4 + wn] = p;
            }
        }
        return;
    }

    #pragma unroll
    for (int mt = 0; mt < 4; mt++) {
        #pragma unroll
        for (int nt = 0; nt < 4; nt++) {
            int mb = m0 + wm * 64 + mt * 16 + (lane >> 2);
            int nb = n0 + wn * 32 + nt * 8 + (lane & 3) * 2;
            if (nb >= N) continue;
            if (outbf) {
                __nv_bfloat16* C = (__nv_bfloat16*)Cv;
                if (mb < M)
                    *(__nv_bfloat162*)(C + (size_t)mb * ldc + nb) =
                        __floats2bfloat162_rn(acc[mt][nt][0], acc[mt][nt][1]);
                if (mb + 8 < M)
                    *(__nv_bfloat162*)(C + (size_t)(mb + 8) * ldc + nb) =
                        __floats2bfloat162_rn(acc[mt][nt][2], acc[mt][nt][3]);
            } else {
                float* C = (float*)Cv;
                if (mb < M)
                    *(float2*)(C + (size_t)mb * ldc + nb) =
                        make_float2(acc[mt][nt][0], acc[mt][nt][1]);
                if (mb + 8 < M)
                    *(float2*)(C + (size_t)(mb + 8) * ldc + nb) =
                        make_float2(acc[mt][nt][2], acc[mt][nt][3]);
            }
        }
    }
}

// ------------------------- kernel 3: clip-level assemble (staged) ---------
#define ASM_SMEM (8 * WSTK * 2)        /* 73728 bytes */

__global__ void __launch_bounds__(1024) assemble(const float* __restrict__ k_b,
                                                 const float* __restrict__ v_b,
                                                 const float* __restrict__ gamma,
                                                 const float* __restrict__ beta)
{
    extern __shared__ __align__(16) __nv_bfloat16 sf[];
    int clip = blockIdx.x;
    int tid = threadIdx.x;

    const uint4* src = (const uint4*)(d_Ph + (size_t)clip * 8 * WSTK);
    uint4* dst = (uint4*)sf;
    #pragma unroll
    for (int i = 0; i < 5; i++) {
        int idx = tid + 1024 * i;
        if (idx < (8 * WSTK) / 8) dst[idx] = src[idx];
    }
    __syncthreads();

    int w = tid >> 5, lane = tid & 31;
    if (w >= TLEN) return;
    int fa = c_TA[w], fb = c_TB[w];
    int r = (clip < NS) ? clip * TLEN + w : SROWS + (clip - NS) * TLEN + w;

    const __nv_bfloat162* A2 = (const __nv_bfloat162*)(sf + fa * WSTK);
    const __nv_bfloat162* B2 = (const __nv_bfloat162*)(sf + fb * WSTK);
    const float2* kb2 = (const float2*)k_b;
    const float2* vb2 = (const float2*)v_b;
    __nv_bfloat162* vout = (__nv_bfloat162*)(d_VSh + (size_t)r * DOUT);

    float s1 = 0.f, s2 = 0.f, vn = 0.f;
    #pragma unroll 6
    for (int i = 0; i < 18; i++) {
        int j2 = lane + 32 * i;
        __nv_bfloat162 ka = A2[j2];
        __nv_bfloat162 kb = B2[DOUT / 2 + j2];
        float2 kbias = kb2[j2];
        float k0 = __low2float(ka)  + __low2float(kb)  + kbias.x;
        float k1 = __high2float(ka) + __high2float(kb) + kbias.y;
        s1 += k0 + k1; s2 += k0 * k0 + k1 * k1;
        __nv_bfloat162 va = A2[DOUT + j2];
        __nv_bfloat162 vb = B2[3 * DOUT / 2 + j2];
        float2 vbias = vb2[j2];
        float v0 = __low2float(va)  + __low2float(vb)  + vbias.x;
        float v1 = __high2float(va) + __high2float(vb) + vbias.y;
        vn += v0 * v0 + v1 * v1;
        vout[j2] = __floats2bfloat162_rn(v0, v1);
    }
    #pragma unroll
    for (int s = 16; s > 0; s >>= 1) {
        s1 += __shfl_xor_sync(0xffffffffu, s1, s);
        s2 += __shfl_xor_sync(0xffffffffu, s2, s);
        vn += __shfl_xor_sync(0xffffffffu, vn, s);
    }
    float mu  = s1 / (float)DOUT;
    float var = s2 / (float)DOUT - mu * mu;
    float inv = rsqrtf(var + LN_EPS);

    const float2* g2 = (const float2*)gamma;
    const float2* b2 = (const float2*)beta;
    __nv_bfloat162* kout = (__nv_bfloat162*)(d_KSh + (size_t)r * DOUT);
    #pragma unroll 6
    for (int i = 0; i < 18; i++) {
        int j2 = lane + 32 * i;
        __nv_bfloat162 ka = A2[j2];
        __nv_bfloat162 kb = B2[DOUT / 2 + j2];
        float2 kbias = kb2[j2];
        float k0 = __low2float(ka)  + __low2float(kb)  + kbias.x;
        float k1 = __high2float(ka) + __high2float(kb) + kbias.y;
        float2 g = g2[j2], bt = b2[j2];
        kout[j2] = __floats2bfloat162_rn((k0 - mu) * inv * g.x + bt.x,
                                         (k1 - mu) * inv * g.y + bt.y);
    }
    if (lane == 0) d_VN[r] = vn;
}

// ------------------------- kernel 4: softmax (2 rows per block) -----------
__global__ void softmax_k(float scale) {
    int row  = blockIdx.x * 2 + (threadIdx.x >= 160 ? 1 : 0);
    int t    = threadIdx.x >= 160 ? threadIdx.x - 160 : threadIdx.x;
    int c    = t >> 5;
    int lane = t & 31;
    const float* p = d_QK + (size_t)row * SROWS + c * CLS;
    __nv_bfloat16* pb = d_Ab + (size_t)row * ABLD + c * CPAD;

    float v[5];
    float mx = -1e30f;
    #pragma unroll
    for (int i = 0; i < 5; i++) {
        int j = lane + 32 * i;
        v[i] = (j < CLS) ? p[j] * scale : -1e30f;
        mx = fmaxf(mx, v[i]);
    }
    #pragma unroll
    for (int s = 16; s > 0; s >>= 1) mx = fmaxf(mx, __shfl_xor_sync(0xffffffffu, mx, s));
    float sum = 0.f;
    #pragma unroll
    for (int i = 0; i < 5; i++) {
        int j = lane + 32 * i;
        if (j < CLS) { v[i] = expf(v[i] - mx); sum += v[i]; }
    }
    #pragma unroll
    for (int s = 16; s > 0; s >>= 1) sum += __shfl_xor_sync(0xffffffffu, sum, s);
    float invs = 1.0f / sum;
    #pragma unroll
    for (int i = 0; i < 5; i++) {
        int j = lane + 32 * i;
        if (j < CLS) pb[j] = __float2bfloat16(v[i] * invs);
    }
}

// ------------------------- kernel 5: tiny final reduction -----------------
__global__ void final_k(const float* __restrict__ gt, const float* __restrict__ tw,
                        float* __restrict__ out)
{
    int q = blockIdx.x;
    int c = threadIdx.x >> 5;
    int lane = threadIdx.x & 31;
    float temp = gt[0] * tw[0];

    float tot = 0.f;
    if (lane < TLEN) {
        tot = d_VN[SROWS + q * TLEN + lane];
        const float* dd = d_D2 + ((size_t)c * QROWS + q * TLEN + lane) * 8;
        float4 x = *(const float4*)dd;
        float4 y = *(const float4*)(dd + 4);
        tot += x.x + x.y + x.z + x.w + y.x + y.y + y.z + y.w;
    }
    #pragma unroll
    for (int s = 16; s > 0; s >>= 1) tot += __shfl_xor_sync(0xffffffffu, tot, s);
    if (lane == 0) out[q * WAY + c] = -(tot / (float)TLEN) * temp;
}

// ------------------------- launch -----------------------------------------
extern "C" void kernel_launch(void* const* d_in, const int* in_sizes, int n_in,
                              void* d_out, int out_size) {
    const float* sup   = (const float*)d_in[0];
    const float* qry   = (const float*)d_in[2];
    const float* k_w   = (const float*)d_in[3];
    const float* k_b   = (const float*)d_in[4];
    const float* v_w   = (const float*)d_in[5];
    const float* v_b   = (const float*)d_in[6];
    const float* gamma = (const float*)d_in[7];
    const float* beta  = (const float*)d_in[8];
    const float* gt    = (const float*)d_in[9];
    const float* tw    = (const float*)d_in[10];
    float* out = (float*)d_out;

    __nv_bfloat16 *pXh, *pWT, *pPh, *pKSh, *pVSh, *pAb, *pSSh;
    float *pQK, *pQV, *pD2;
    cudaGetSymbolAddress((void**)&pXh,  d_Xh);
    cudaGetSymbolAddress((void**)&pWT,  d_WT);
    cudaGetSymbolAddress((void**)&pPh,  d_Ph);
    cudaGetSymbolAddress((void**)&pKSh, d_KSh);
    cudaGetSymbolAddress((void**)&pVSh, d_VSh);
    cudaGetSymbolAddress((void**)&pQK,  d_QK);
    cudaGetSymbolAddress((void**)&pQV,  d_QV);
    cudaGetSymbolAddress((void**)&pD2,  d_D2);
    cudaGetSymbolAddress((void**)&pAb,  d_Ab);
    cudaGetSymbolAddress((void**)&pSSh, d_SSh);

    cudaFuncSetAttribute(pgemm,    cudaFuncAttributeMaxDynamicSharedMemorySize, PG_SMEM);
    cudaFuncSetAttribute(mgemm<2>, cudaFuncAttributeMaxDynamicSharedMemorySize, MG_SMEM);
    cudaFuncSetAttribute(mgemm<3>, cudaFuncAttributeMaxDynamicSharedMemorySize, MG_SMEM);
    cudaFuncSetAttribute(assemble, cudaFuncAttributeMaxDynamicSharedMemorySize, ASM_SMEM);

    build_x<<<(NFRAMES * FEAT / 8 + 255) / 256, 256>>>(sup, qry);
    wtrans<<<dim3(DOUT / 32, FEAT / 32, 4), dim3(32, 8)>>>(k_w, v_w);

    // Projections (bf16 out): Ph[4200, 4608] = Xh @ WT^T  (128x256 tiles)
    {
        dim3 g((WSTK + 255) / 256, (NFRAMES + 127) / 128);
        pgemm<<<g, 256, PG_SMEM>>>(pXh, pWT, pPh, NFRAMES, WSTK, FEAT, FEAT, FEAT, WSTK);
    }

    assemble<<<CLIPS, 1024, ASM_SMEM>>>(k_b, v_b, gamma, beta);

    // Merged QK + QV + per-class SS Gram (grid (6, 112, 2))
    {
        BatchArg ba = {};
        ba.p[0] = { pKSh + (size_t)SROWS * DOUT, pKSh, (void*)pQK, nullptr };
        ba.p[1] = { pVSh + (size_t)SROWS * DOUT, pVSh, (void*)pQV, nullptr };
        ba.p[2] = { pVSh, nullptr, (void*)pSSh, nullptr };
        dim3 g(6, QYT + 2, 2);
        mgemm<3><<<g, 256, MG_SMEM>>>(ba, 0, 0, 0, 0, 0, 0, nullptr);
    }

    softmax_k<<<QROWS / 2, 320>>>(1.0f / sqrtf((float)DOUT));

    // Fused H + distance partials (z=5)
    {
        BatchArg ba = {};
        for (int c = 0; c < WAY; c++)
            ba.p[c] = { pAb + (size_t)c * CPAD,
                        pSSh + (size_t)c * CLS * CPAD,
                        nullptr,
                        pQV + (size_t)c * CLS };
        dim3 g((CLS + 127) / 128, (QROWS + 127) / 128, WAY);
        mgemm<2><<<g, 256, MG_SMEM>>>(ba, QROWS, CLS, CLS, ABLD, CPAD, SROWS, pD2);
    }

    final_k<<<NQ, 160>>>(gt, tw, out);
}